// round 16
// baseline (speedup 1.0000x reference)
#include <cuda_runtime.h>
#include <cstdint>

typedef unsigned long long U64;

// ---------------- static device scratch ----------------
__device__ float g_xp[16778240];   // [2][64][1024][128] + pad (deep-prefetch overrun)
__device__ float g_h0[4194304];    // [64][1024][64]
__device__ float g_h1[4194304];    // [64][1024][64]
__device__ float g_part1[8388608]; // [64][64][2048] fc1 split-K partials
__device__ float g_hidden[131072]; // [64][2048]
__device__ float g_part2[4718592]; // [8][64][9216] fc2 split-K partials

// ---------------- helpers ----------------
__device__ __forceinline__ void ffma2(U64 &acc, U64 a, U64 b){
    asm("fma.rn.f32x2 %0, %1, %2, %0;" : "+l"(acc) : "l"(a), "l"(b));
}
__device__ __forceinline__ U64 add2(U64 a, U64 b){
    U64 r; asm("add.rn.f32x2 %0, %1, %2;" : "=l"(r) : "l"(a), "l"(b)); return r;
}
__device__ __forceinline__ float2 unpk(U64 v){
    float2 r; asm("mov.b64 {%0, %1}, %2;" : "=f"(r.x), "=f"(r.y) : "l"(v)); return r;
}
__device__ __forceinline__ float sum2(U64 v){ float2 r = unpk(v); return r.x + r.y; }
__device__ __forceinline__ float tanha(float x){ float r; asm("tanh.approx.f32 %0, %1;" : "=f"(r) : "f"(x)); return r; }
__device__ __forceinline__ float siga (float x){ return fmaf(0.5f, tanha(0.5f * x), 0.5f); }

// cvt: word = { hi16: bf16(b), lo16: bf16(a) }
__device__ __forceinline__ uint32_t cvt_bf2(float a, float b){
    uint32_t r; asm("cvt.rn.bf16x2.f32 %0, %1, %2;" : "=r"(r) : "f"(b), "f"(a)); return r;
}
__device__ __forceinline__ uint32_t smem_u32(const void* p){
    uint32_t a; asm("{ .reg .u64 t; cvta.to.shared.u64 t, %1; cvt.u32.u64 %0, t; }" : "=r"(a) : "l"(p));
    return a;
}
__device__ __forceinline__ void ldm4(uint32_t* r, uint32_t addr){
    asm volatile("ldmatrix.sync.aligned.m8n8.x4.shared.b16 {%0,%1,%2,%3}, [%4];"
        : "=r"(r[0]), "=r"(r[1]), "=r"(r[2]), "=r"(r[3]) : "r"(addr));
}
__device__ __forceinline__ void mma_bf(float (&d)[4], const uint32_t* a, uint32_t b0, uint32_t b1){
    asm volatile("mma.sync.aligned.m16n8k16.row.col.f32.bf16.bf16.f32 "
        "{%0,%1,%2,%3}, {%4,%5,%6,%7}, {%8,%9}, {%0,%1,%2,%3};"
        : "+f"(d[0]), "+f"(d[1]), "+f"(d[2]), "+f"(d[3])
        : "r"(a[0]), "r"(a[1]), "r"(a[2]), "r"(a[3]), "r"(b0), "r"(b1));
}

#define TW 132   // padded smem row stride (floats) for xproj kernels

// ---------------- xproj layer 0: tiled, K=9 ----------------
__global__ void __launch_bounds__(256) xproj0_kernel(const float* __restrict__ x,
    const float* __restrict__ wf, const float* __restrict__ bif, const float* __restrict__ bhf,
    const float* __restrict__ wr, const float* __restrict__ bir, const float* __restrict__ bhr)
{
    __shared__ float ws[9 * TW];
    __shared__ float fs[9 * TW];
    const int tid = threadIdx.x;
    const int s0 = blockIdx.x * 64;
    const int b  = blockIdx.y;
    const int d  = blockIdx.z;
    const float* w  = d ? wr : wf;
    const float* bi = d ? bir : bif;
    const float* bh = d ? bhr : bhf;

    if (tid < 128){
        const float* src = w + tid * 9;
        #pragma unroll
        for (int k = 0; k < 9; k++) ws[k * TW + tid] = src[k];
    } else if (tid < 192){
        int r = tid - 128;
        int s = s0 + r;
        int tsrc = d ? (1023 - s) : s;
        const float* src = x + ((size_t)b * 1024 + tsrc) * 9;
        #pragma unroll
        for (int k = 0; k < 9; k++){
            float v = src[k];
            *(float2*)&fs[k * TW + 2 * r] = make_float2(v, v);
        }
    }
    __syncthreads();

    const int nq = tid & 15;
    const int bq = tid >> 4;
    U64 acc[4][4];
    #pragma unroll
    for (int i = 0; i < 4; i++)
        #pragma unroll
        for (int j = 0; j < 4; j++) acc[i][j] = 0ull;

    #pragma unroll
    for (int kk = 0; kk < 9; kk++){
        ulonglong2 wa = *(const ulonglong2*)&ws[kk*TW + nq*4];
        ulonglong2 wb = *(const ulonglong2*)&ws[kk*TW + 64 + nq*4];
        ulonglong2 xa = *(const ulonglong2*)&fs[kk*TW + bq*8];
        ulonglong2 xc = *(const ulonglong2*)&fs[kk*TW + bq*8 + 4];
        U64 xv0 = xa.x, xv1 = xa.y, xv2 = xc.x, xv3 = xc.y;
        ffma2(acc[0][0], xv0, wa.x); ffma2(acc[0][1], xv0, wa.y);
        ffma2(acc[0][2], xv0, wb.x); ffma2(acc[0][3], xv0, wb.y);
        ffma2(acc[1][0], xv1, wa.x); ffma2(acc[1][1], xv1, wa.y);
        ffma2(acc[1][2], xv1, wb.x); ffma2(acc[1][3], xv1, wb.y);
        ffma2(acc[2][0], xv2, wa.x); ffma2(acc[2][1], xv2, wa.y);
        ffma2(acc[2][2], xv2, wb.x); ffma2(acc[2][3], xv2, wb.y);
        ffma2(acc[3][0], xv3, wa.x); ffma2(acc[3][1], xv3, wa.y);
        ffma2(acc[3][2], xv3, wb.x); ffma2(acc[3][3], xv3, wb.y);
    }

    int j0 = nq * 4, j1 = 64 + nq * 4;
    float bv[8];
    #pragma unroll
    for (int q = 0; q < 4; q++){ bv[q] = bi[j0+q] + bh[j0+q]; bv[4+q] = bi[j1+q] + bh[j1+q]; }

    float* base = g_xp + ((size_t)(d * 64 + b) * 1024 + s0) * 128;
    #pragma unroll
    for (int b4 = 0; b4 < 4; b4++){
        float* dst = base + (size_t)(bq * 4 + b4) * 128;
        float2 v0 = unpk(acc[b4][0]); v0.x += bv[0]; v0.y += bv[1];
        float2 v1 = unpk(acc[b4][1]); v1.x += bv[2]; v1.y += bv[3];
        float2 v2 = unpk(acc[b4][2]); v2.x += bv[4]; v2.y += bv[5];
        float2 v3 = unpk(acc[b4][3]); v3.x += bv[6]; v3.y += bv[7];
        *(float2*)(dst + j0)     = v0;
        *(float2*)(dst + j0 + 2) = v1;
        *(float2*)(dst + j1)     = v2;
        *(float2*)(dst + j1 + 2) = v3;
    }
}

// ---------------- xproj layer 1: tiled GEMM, K=64 ----------------
__global__ void __launch_bounds__(256) xproj1_kernel(
    const float* __restrict__ wf, const float* __restrict__ bif, const float* __restrict__ bhf,
    const float* __restrict__ wr, const float* __restrict__ bir, const float* __restrict__ bhr)
{
    __shared__ float ws[32 * TW];
    __shared__ float fs[32 * TW];
    const int tid = threadIdx.x;
    const int s0 = blockIdx.x * 64;
    const int b  = blockIdx.y;
    const int d  = blockIdx.z;
    const float* w  = d ? wr : wf;
    const float* bi = d ? bir : bif;
    const float* bh = d ? bhr : bhf;

    const int sn  = tid & 127, skq = tid >> 7;
    const int xr  = tid & 63,  xkq = tid >> 6;
    int s = s0 + xr;
    int tsrc = d ? (1023 - s) : s;
    const float* wptr = w + sn * 64 + skq * 16;
    const float* hptr = g_h0 + ((size_t)b * 1024 + tsrc) * 64 + xkq * 8;

    const int nq = tid & 15;
    const int bq = tid >> 4;
    U64 acc[4][4];
    #pragma unroll
    for (int i = 0; i < 4; i++)
        #pragma unroll
        for (int j = 0; j < 4; j++) acc[i][j] = 0ull;

    #pragma unroll
    for (int ch = 0; ch < 2; ch++){
        if (ch){ __syncthreads(); }
        {
            const float4* src = (const float4*)(wptr + ch * 32);
            float4 v0 = src[0], v1 = src[1], v2 = src[2], v3 = src[3];
            int kb = skq * 16;
            ws[(kb+ 0)*TW + sn] = v0.x; ws[(kb+ 1)*TW + sn] = v0.y;
            ws[(kb+ 2)*TW + sn] = v0.z; ws[(kb+ 3)*TW + sn] = v0.w;
            ws[(kb+ 4)*TW + sn] = v1.x; ws[(kb+ 5)*TW + sn] = v1.y;
            ws[(kb+ 6)*TW + sn] = v1.z; ws[(kb+ 7)*TW + sn] = v1.w;
            ws[(kb+ 8)*TW + sn] = v2.x; ws[(kb+ 9)*TW + sn] = v2.y;
            ws[(kb+10)*TW + sn] = v2.z; ws[(kb+11)*TW + sn] = v2.w;
            ws[(kb+12)*TW + sn] = v3.x; ws[(kb+13)*TW + sn] = v3.y;
            ws[(kb+14)*TW + sn] = v3.z; ws[(kb+15)*TW + sn] = v3.w;
        }
        {
            const float4* src = (const float4*)(hptr + ch * 32);
            float4 u0 = src[0], u1 = src[1];
            int kb = xkq * 8;
            *(float2*)&fs[(kb+0)*TW + 2*xr] = make_float2(u0.x, u0.x);
            *(float2*)&fs[(kb+1)*TW + 2*xr] = make_float2(u0.y, u0.y);
            *(float2*)&fs[(kb+2)*TW + 2*xr] = make_float2(u0.z, u0.z);
            *(float2*)&fs[(kb+3)*TW + 2*xr] = make_float2(u0.w, u0.w);
            *(float2*)&fs[(kb+4)*TW + 2*xr] = make_float2(u1.x, u1.x);
            *(float2*)&fs[(kb+5)*TW + 2*xr] = make_float2(u1.y, u1.y);
            *(float2*)&fs[(kb+6)*TW + 2*xr] = make_float2(u1.z, u1.z);
            *(float2*)&fs[(kb+7)*TW + 2*xr] = make_float2(u1.w, u1.w);
        }
        __syncthreads();
        #pragma unroll
        for (int kk = 0; kk < 32; kk++){
            ulonglong2 wa = *(const ulonglong2*)&ws[kk*TW + nq*4];
            ulonglong2 wb = *(const ulonglong2*)&ws[kk*TW + 64 + nq*4];
            ulonglong2 xa = *(const ulonglong2*)&fs[kk*TW + bq*8];
            ulonglong2 xc = *(const ulonglong2*)&fs[kk*TW + bq*8 + 4];
            U64 xv0 = xa.x, xv1 = xa.y, xv2 = xc.x, xv3 = xc.y;
            ffma2(acc[0][0], xv0, wa.x); ffma2(acc[0][1], xv0, wa.y);
            ffma2(acc[0][2], xv0, wb.x); ffma2(acc[0][3], xv0, wb.y);
            ffma2(acc[1][0], xv1, wa.x); ffma2(acc[1][1], xv1, wa.y);
            ffma2(acc[1][2], xv1, wb.x); ffma2(acc[1][3], xv1, wb.y);
            ffma2(acc[2][0], xv2, wa.x); ffma2(acc[2][1], xv2, wa.y);
            ffma2(acc[2][2], xv2, wb.x); ffma2(acc[2][3], xv2, wb.y);
            ffma2(acc[3][0], xv3, wa.x); ffma2(acc[3][1], xv3, wa.y);
            ffma2(acc[3][2], xv3, wb.x); ffma2(acc[3][3], xv3, wb.y);
        }
    }

    int j0 = nq * 4, j1 = 64 + nq * 4;
    float bv[8];
    #pragma unroll
    for (int q = 0; q < 4; q++){ bv[q] = bi[j0+q] + bh[j0+q]; bv[4+q] = bi[j1+q] + bh[j1+q]; }

    float* base = g_xp + ((size_t)(d * 64 + b) * 1024 + s0) * 128;
    #pragma unroll
    for (int b4 = 0; b4 < 4; b4++){
        float* dst = base + (size_t)(bq * 4 + b4) * 128;
        float2 v0 = unpk(acc[b4][0]); v0.x += bv[0]; v0.y += bv[1];
        float2 v1 = unpk(acc[b4][1]); v1.x += bv[2]; v1.y += bv[3];
        float2 v2 = unpk(acc[b4][2]); v2.x += bv[4]; v2.y += bv[5];
        float2 v3 = unpk(acc[b4][3]); v3.x += bv[6]; v3.y += bv[7];
        *(float2*)(dst + j0)     = v0;
        *(float2*)(dst + j0 + 2) = v1;
        *(float2*)(dst + j1)     = v2;
        *(float2*)(dst + j1 + 2) = v3;
    }
}

// ---------------- LSTM: ONE warp per (dir,batch) — no block barrier ----------------
__global__ void __launch_bounds__(32, 1) lstm_kernel(
    const float* __restrict__ whh_f, const float* __restrict__ whh_r, int outsel)
{
    const int blk = blockIdx.x;          // 0..127
    const int d = blk >> 6, b = blk & 63;
    const int hh = threadIdx.x;          // hidden unit
    float* hout = outsel ? g_h1 : g_h0;
    const float* whh = d ? whh_r : whh_f;

    // all 4 gate rows for unit hh: 4 x 32 floats = 64 U64 regs
    U64 wp[4][16];
    #pragma unroll
    for (int g = 0; g < 4; g++){
        const ulonglong2* wr2 = (const ulonglong2*)(whh + (g * 32 + hh) * 32);
        #pragma unroll
        for (int r = 0; r < 8; r++){ ulonglong2 v = wr2[r]; wp[g][2*r] = v.x; wp[g][2*r+1] = v.y; }
    }

    __shared__ __align__(16) float hs[32];
    hs[hh] = 0.0f;
    float c = 0.0f;
    __syncwarp();

    const float* xq = g_xp + (size_t)(d * 64 + b) * 1024 * 128 + hh;
    float* outp = hout + (size_t)b * 1024 * 64 + d * 32 + hh;

    // 4-deep prefetch: cur holds steps s..s+3 (4 gates each)
    float cur[4][4];
    #pragma unroll
    for (int t = 0; t < 4; t++)
        #pragma unroll
        for (int g = 0; g < 4; g++) cur[t][g] = xq[(size_t)t * 128 + g * 32];

    #define LSTM_STEP(SS, X0, X1, X2, X3)                                     \
    {                                                                         \
        U64 a0 = 0ull, a1 = 0ull, a2 = 0ull, a3 = 0ull;                       \
        U64 a4 = 0ull, a5 = 0ull, a6 = 0ull, a7 = 0ull;                       \
        const ulonglong2* h2 = (const ulonglong2*)hs;                         \
        _Pragma("unroll")                                                     \
        for (int r = 0; r < 8; r++){                                          \
            ulonglong2 hv = h2[r];                                            \
            ffma2(a0, hv.x, wp[0][2*r]); ffma2(a1, hv.y, wp[0][2*r+1]);       \
            ffma2(a2, hv.x, wp[1][2*r]); ffma2(a3, hv.y, wp[1][2*r+1]);       \
            ffma2(a4, hv.x, wp[2][2*r]); ffma2(a5, hv.y, wp[2][2*r+1]);       \
            ffma2(a6, hv.x, wp[3][2*r]); ffma2(a7, hv.y, wp[3][2*r+1]);       \
        }                                                                     \
        float iv = siga ((X0) + sum2(add2(a0, a1)));                          \
        float fv = siga ((X1) + sum2(add2(a2, a3)));                          \
        float gv = tanha((X2) + sum2(add2(a4, a5)));                          \
        float ov = siga ((X3) + sum2(add2(a6, a7)));                          \
        c = fmaf(fv, c, iv * gv);                                             \
        float hval = ov * tanha(c);                                           \
        hs[hh] = hval;                                                        \
        __syncwarp();                                                         \
        int tout = d ? (1023 - (SS)) : (SS);                                  \
        outp[(size_t)tout * 64] = hval;                                       \
    }

    for (int s = 0; s < 1024; s += 4){
        // issue loads for steps s+4..s+7 (consumed a full group later)
        const float* q = xq + (size_t)(s + 4) * 128;
        float nx[4][4];
        #pragma unroll
        for (int t = 0; t < 4; t++)
            #pragma unroll
            for (int g = 0; g < 4; g++) nx[t][g] = q[(size_t)t * 128 + g * 32];

        LSTM_STEP(s + 0, cur[0][0], cur[0][1], cur[0][2], cur[0][3])
        LSTM_STEP(s + 1, cur[1][0], cur[1][1], cur[1][2], cur[1][3])
        LSTM_STEP(s + 2, cur[2][0], cur[2][1], cur[2][2], cur[2][3])
        LSTM_STEP(s + 3, cur[3][0], cur[3][1], cur[3][2], cur[3][3])

        #pragma unroll
        for (int t = 0; t < 4; t++)
            #pragma unroll
            for (int g = 0; g < 4; g++) cur[t][g] = nx[t][g];
    }
    #undef LSTM_STEP
}

// ---------------- fc via mma.sync bf16 3-term split (fc1 & fc2) ----------------
#define MB_WH 0
#define MB_WL 8192
#define MB_XH 16384
#define MB_XL 20480
#define MB_BUF 24576

__global__ void __launch_bounds__(128) fc_mma_kernel(
    const float* __restrict__ W, const float* __restrict__ Xg,
    float* __restrict__ part, int K, int N, int nchunks)
{
    __shared__ __align__(128) char smb[2 * MB_BUF];  // 48KB
    const int tid  = threadIdx.x;
    const int lane = tid & 31;
    const int wid  = tid >> 5;
    const int m0out  = blockIdx.x * 128;
    const int kstart = blockIdx.y * (nchunks * 32);

    const int kq    = tid & 7;
    const int rbase = tid >> 3;

    const float* wg = W  + (size_t)(m0out + rbase) * K + kstart + kq * 4;
    const float* xg = Xg + (size_t)rbase * K + kstart + kq * 4;

    const uint32_t sb = smem_u32(smb);

    const int arow = wid * 16 + ((lane >> 3) & 1) * 8 + (lane & 7);
    const int asw  = (arow >> 1) & 3;
    const int akb  = lane >> 4;
    const uint32_t aoff = (uint32_t)(arow * 64);
    const int brow = ((lane >> 4) & 1) * 8 + (lane & 7);
    const int bsw  = (brow >> 1) & 3;
    const int bkb  = (lane >> 3) & 1;
    const uint32_t boff = (uint32_t)(brow * 64);

    float acc[16][4];
    #pragma unroll
    for (int i = 0; i < 16; i++)
        #pragma unroll
        for (int j = 0; j < 4; j++) acc[i][j] = 0.0f;

    float4 wv[8], xv[4];
    #pragma unroll
    for (int i = 0; i < 8; i++) wv[i] = *(const float4*)(wg + (size_t)i * 16 * K);
    #pragma unroll
    for (int i = 0; i < 4; i++) xv[i] = *(const float4*)(xg + (size_t)i * 16 * K);

    const int so_base = (kq & 1) * 8;
    for (int ch = 0; ch < nchunks; ch++){
        char* bufc = smb + (ch & 1) * MB_BUF;
        #pragma unroll
        for (int i = 0; i < 8; i++){
            float4 v = wv[i];
            int row = rbase + i * 16;
            uint32_t h0 = cvt_bf2(v.x, v.y);
            uint32_t l0 = cvt_bf2(v.x - __uint_as_float(h0 << 16),
                                  v.y - __uint_as_float(h0 & 0xFFFF0000u));
            uint32_t h1 = cvt_bf2(v.z, v.w);
            uint32_t l1 = cvt_bf2(v.z - __uint_as_float(h1 << 16),
                                  v.w - __uint_as_float(h1 & 0xFFFF0000u));
            int so = row * 64 + ((((kq >> 1) ^ ((row >> 1) & 3)) << 4) | so_base);
            *(uint2*)(bufc + MB_WH + so) = make_uint2(h0, h1);
            *(uint2*)(bufc + MB_WL + so) = make_uint2(l0, l1);
        }
        #pragma unroll
        for (int i = 0; i < 4; i++){
            float4 v = xv[i];
            int row = rbase + i * 16;
            uint32_t h0 = cvt_bf2(v.x, v.y);
            uint32_t l0 = cvt_bf2(v.x - __uint_as_float(h0 << 16),
                                  v.y - __uint_as_float(h0 & 0xFFFF0000u));
            uint32_t h1 = cvt_bf2(v.z, v.w);
            uint32_t l1 = cvt_bf2(v.z - __uint_as_float(h1 << 16),
                                  v.w - __uint_as_float(h1 & 0xFFFF0000u));
            int so = row * 64 + ((((kq >> 1) ^ ((row >> 1) & 3)) << 4) | so_base);
            *(uint2*)(bufc + MB_XH + so) = make_uint2(h0, h1);
            *(uint2*)(bufc + MB_XL + so) = make_uint2(l0, l1);
        }
        __syncthreads();

        if (ch + 1 < nchunks){
            #pragma unroll
            for (int i = 0; i < 8; i++) wv[i] = *(const float4*)(wg + (size_t)i * 16 * K + (ch + 1) * 32);
            #pragma unroll
            for (int i = 0; i < 4; i++) xv[i] = *(const float4*)(xg + (size_t)i * 16 * K + (ch + 1) * 32);
        }

        const uint32_t sbuf = sb + (ch & 1) * MB_BUF;
        #pragma unroll
        for (int kt = 0; kt < 2; kt++){
            uint32_t ahi[4], alo[4];
            uint32_t aaddr = sbuf + MB_XH + aoff + (uint32_t)((((kt << 1) | akb) ^ asw) << 4);
            ldm4(ahi, aaddr);
            ldm4(alo, aaddr + (MB_XL - MB_XH));
            #pragma unroll
            for (int ntp = 0; ntp < 8; ntp++){
                uint32_t bhi[4], blo[4];
                uint32_t baddr = sbuf + MB_WH + (uint32_t)(ntp * 1024) + boff
                               + (uint32_t)((((kt << 1) | bkb) ^ bsw) << 4);
                ldm4(bhi, baddr);
                ldm4(blo, baddr + (MB_WL - MB_WH));
                mma_bf(acc[2*ntp],   ahi, bhi[0], bhi[1]);
                mma_bf(acc[2*ntp],   alo, bhi[0], bhi[1]);
                mma_bf(acc[2*ntp],   ahi, blo[0], blo[1]);
                mma_bf(acc[2*ntp+1], ahi, bhi[2], bhi[3]);
                mma_bf(acc[2*ntp+1], alo, bhi[2], bhi[3]);
                mma_bf(acc[2*ntp+1], ahi, blo[2], blo[3]);
            }
        }
        __syncthreads();
    }

    {
        int bat  = wid * 16 + (lane >> 2);
        int colb = m0out + (lane & 3) * 2;
        float* d0 = part + ((size_t)blockIdx.y * 64 + bat) * N + colb;
        float* d1 = d0 + (size_t)8 * N;
        #pragma unroll
        for (int nt = 0; nt < 16; nt++){
            *(float2*)(d0 + nt * 8) = make_float2(acc[nt][0], acc[nt][1]);
            *(float2*)(d1 + nt * 8) = make_float2(acc[nt][2], acc[nt][3]);
        }
    }
}

// ---------------- split-K reductions ----------------
__global__ void reduce1_kernel(const float* __restrict__ bias){
    int i = blockIdx.x * 256 + threadIdx.x;   // 131072
    int m = i & 2047, b = i >> 11;
    float acc = bias[m];
    #pragma unroll
    for (int s = 0; s < 64; s++) acc += g_part1[((size_t)s * 64 + b) * 2048 + m];
    g_hidden[i] = fmaxf(acc, 0.0f);
}

__global__ void reduce2_kernel(const float* __restrict__ bias, float* __restrict__ out){
    int i = blockIdx.x * 256 + threadIdx.x;   // 589824
    int n = i % 9216, b = i / 9216;
    float acc = bias[n];
    #pragma unroll
    for (int s = 0; s < 8; s++) acc += g_part2[((size_t)s * 64 + b) * 9216 + n];
    out[i] = acc;
}

// ---------------- launcher ----------------
extern "C" void kernel_launch(void* const* d_in, const int* in_sizes, int n_in,
                              void* d_out, int out_size)
{
    const float* x     = (const float*)d_in[0];
    const float* wih0  = (const float*)d_in[1];
    const float* whh0  = (const float*)d_in[2];
    const float* bih0  = (const float*)d_in[3];
    const float* bhh0  = (const float*)d_in[4];
    const float* wih0r = (const float*)d_in[5];
    const float* whh0r = (const float*)d_in[6];
    const float* bih0r = (const float*)d_in[7];
    const float* bhh0r = (const float*)d_in[8];
    const float* wih1  = (const float*)d_in[9];
    const float* whh1  = (const float*)d_in[10];
    const float* bih1  = (const float*)d_in[11];
    const float* bhh1  = (const float*)d_in[12];
    const float* wih1r = (const float*)d_in[13];
    const float* whh1r = (const float*)d_in[14];
    const float* bih1r = (const float*)d_in[15];
    const float* bhh1r = (const float*)d_in[16];
    const float* fc1w  = (const float*)d_in[17];
    const float* fc1b  = (const float*)d_in[18];
    const float* fc2w  = (const float*)d_in[19];
    const float* fc2b  = (const float*)d_in[20];
    float* out = (float*)d_out;

    float* d_h1;     cudaGetSymbolAddress((void**)&d_h1,     g_h1);
    float* d_hidden; cudaGetSymbolAddress((void**)&d_hidden, g_hidden);
    float* d_part1;  cudaGetSymbolAddress((void**)&d_part1,  g_part1);
    float* d_part2;  cudaGetSymbolAddress((void**)&d_part2,  g_part2);

    xproj0_kernel<<<dim3(16, 64, 2), 256>>>(x, wih0, bih0, bhh0, wih0r, bih0r, bhh0r);
    lstm_kernel<<<128, 32>>>(whh0, whh0r, 0);
    xproj1_kernel<<<dim3(16, 64, 2), 256>>>(wih1, bih1, bhh1, wih1r, bih1r, bhh1r);
    lstm_kernel<<<128, 32>>>(whh1, whh1r, 1);

    // fc1: grid (16 wrow-tiles of 128, 64 k-splits of 1024 => 32 chunks)
    fc_mma_kernel<<<dim3(16, 64), 128>>>(fc1w, d_h1, d_part1, 65536, 2048, 32);
    reduce1_kernel<<<512, 256>>>(fc1b);

    // fc2: grid (72 wrow-tiles of 128, 8 k-splits of 256 => 8 chunks)
    fc_mma_kernel<<<dim3(72, 8), 128>>>(fc2w, d_hidden, d_part2, 2048, 9216, 8);
    reduce2_kernel<<<2304, 256>>>(fc2b, out);
}

// round 17
// speedup vs baseline: 1.0988x; 1.0988x over previous
#include <cuda_runtime.h>
#include <cstdint>

typedef unsigned long long U64;

// ---------------- static device scratch ----------------
__device__ float g_xp[16778240];   // [2][64][1024][128] + pad (deep-prefetch overrun)
__device__ float g_h0[4194304];    // [64][1024][64]
__device__ float g_h1[4194304];    // [64][1024][64]
__device__ float g_part1[8388608]; // [64][64][2048] fc1 split-K partials
__device__ float g_hidden[131072]; // [64][2048]
__device__ float g_part2[4718592]; // [8][64][9216] fc2 split-K partials

// ---------------- helpers ----------------
__device__ __forceinline__ void ffma2(U64 &acc, U64 a, U64 b){
    asm("fma.rn.f32x2 %0, %1, %2, %0;" : "+l"(acc) : "l"(a), "l"(b));
}
__device__ __forceinline__ U64 add2(U64 a, U64 b){
    U64 r; asm("add.rn.f32x2 %0, %1, %2;" : "=l"(r) : "l"(a), "l"(b)); return r;
}
__device__ __forceinline__ float2 unpk(U64 v){
    float2 r; asm("mov.b64 {%0, %1}, %2;" : "=f"(r.x), "=f"(r.y) : "l"(v)); return r;
}
__device__ __forceinline__ float sum2(U64 v){ float2 r = unpk(v); return r.x + r.y; }
__device__ __forceinline__ float tanha(float x){ float r; asm("tanh.approx.f32 %0, %1;" : "=f"(r) : "f"(x)); return r; }
__device__ __forceinline__ float siga (float x){ return fmaf(0.5f, tanha(0.5f * x), 0.5f); }

// cvt: word = { hi16: bf16(b), lo16: bf16(a) }
__device__ __forceinline__ uint32_t cvt_bf2(float a, float b){
    uint32_t r; asm("cvt.rn.bf16x2.f32 %0, %1, %2;" : "=r"(r) : "f"(b), "f"(a)); return r;
}
__device__ __forceinline__ uint32_t smem_u32(const void* p){
    uint32_t a; asm("{ .reg .u64 t; cvta.to.shared.u64 t, %1; cvt.u32.u64 %0, t; }" : "=r"(a) : "l"(p));
    return a;
}
__device__ __forceinline__ void ldm4(uint32_t* r, uint32_t addr){
    asm volatile("ldmatrix.sync.aligned.m8n8.x4.shared.b16 {%0,%1,%2,%3}, [%4];"
        : "=r"(r[0]), "=r"(r[1]), "=r"(r[2]), "=r"(r[3]) : "r"(addr));
}
__device__ __forceinline__ void mma_bf(float (&d)[4], const uint32_t* a, uint32_t b0, uint32_t b1){
    asm volatile("mma.sync.aligned.m16n8k16.row.col.f32.bf16.bf16.f32 "
        "{%0,%1,%2,%3}, {%4,%5,%6,%7}, {%8,%9}, {%0,%1,%2,%3};"
        : "+f"(d[0]), "+f"(d[1]), "+f"(d[2]), "+f"(d[3])
        : "r"(a[0]), "r"(a[1]), "r"(a[2]), "r"(a[3]), "r"(b0), "r"(b1));
}

#define TW 132   // padded smem row stride (floats) for xproj kernels

// ---------------- xproj layer 0: tiled, K=9 ----------------
__global__ void __launch_bounds__(256) xproj0_kernel(const float* __restrict__ x,
    const float* __restrict__ wf, const float* __restrict__ bif, const float* __restrict__ bhf,
    const float* __restrict__ wr, const float* __restrict__ bir, const float* __restrict__ bhr)
{
    __shared__ float ws[9 * TW];
    __shared__ float fs[9 * TW];
    const int tid = threadIdx.x;
    const int s0 = blockIdx.x * 64;
    const int b  = blockIdx.y;
    const int d  = blockIdx.z;
    const float* w  = d ? wr : wf;
    const float* bi = d ? bir : bif;
    const float* bh = d ? bhr : bhf;

    if (tid < 128){
        const float* src = w + tid * 9;
        #pragma unroll
        for (int k = 0; k < 9; k++) ws[k * TW + tid] = src[k];
    } else if (tid < 192){
        int r = tid - 128;
        int s = s0 + r;
        int tsrc = d ? (1023 - s) : s;
        const float* src = x + ((size_t)b * 1024 + tsrc) * 9;
        #pragma unroll
        for (int k = 0; k < 9; k++){
            float v = src[k];
            *(float2*)&fs[k * TW + 2 * r] = make_float2(v, v);
        }
    }
    __syncthreads();

    const int nq = tid & 15;
    const int bq = tid >> 4;
    U64 acc[4][4];
    #pragma unroll
    for (int i = 0; i < 4; i++)
        #pragma unroll
        for (int j = 0; j < 4; j++) acc[i][j] = 0ull;

    #pragma unroll
    for (int kk = 0; kk < 9; kk++){
        ulonglong2 wa = *(const ulonglong2*)&ws[kk*TW + nq*4];
        ulonglong2 wb = *(const ulonglong2*)&ws[kk*TW + 64 + nq*4];
        ulonglong2 xa = *(const ulonglong2*)&fs[kk*TW + bq*8];
        ulonglong2 xc = *(const ulonglong2*)&fs[kk*TW + bq*8 + 4];
        U64 xv0 = xa.x, xv1 = xa.y, xv2 = xc.x, xv3 = xc.y;
        ffma2(acc[0][0], xv0, wa.x); ffma2(acc[0][1], xv0, wa.y);
        ffma2(acc[0][2], xv0, wb.x); ffma2(acc[0][3], xv0, wb.y);
        ffma2(acc[1][0], xv1, wa.x); ffma2(acc[1][1], xv1, wa.y);
        ffma2(acc[1][2], xv1, wb.x); ffma2(acc[1][3], xv1, wb.y);
        ffma2(acc[2][0], xv2, wa.x); ffma2(acc[2][1], xv2, wa.y);
        ffma2(acc[2][2], xv2, wb.x); ffma2(acc[2][3], xv2, wb.y);
        ffma2(acc[3][0], xv3, wa.x); ffma2(acc[3][1], xv3, wa.y);
        ffma2(acc[3][2], xv3, wb.x); ffma2(acc[3][3], xv3, wb.y);
    }

    int j0 = nq * 4, j1 = 64 + nq * 4;
    float bv[8];
    #pragma unroll
    for (int q = 0; q < 4; q++){ bv[q] = bi[j0+q] + bh[j0+q]; bv[4+q] = bi[j1+q] + bh[j1+q]; }

    float* base = g_xp + ((size_t)(d * 64 + b) * 1024 + s0) * 128;
    #pragma unroll
    for (int b4 = 0; b4 < 4; b4++){
        float* dst = base + (size_t)(bq * 4 + b4) * 128;
        float2 v0 = unpk(acc[b4][0]); v0.x += bv[0]; v0.y += bv[1];
        float2 v1 = unpk(acc[b4][1]); v1.x += bv[2]; v1.y += bv[3];
        float2 v2 = unpk(acc[b4][2]); v2.x += bv[4]; v2.y += bv[5];
        float2 v3 = unpk(acc[b4][3]); v3.x += bv[6]; v3.y += bv[7];
        *(float2*)(dst + j0)     = v0;
        *(float2*)(dst + j0 + 2) = v1;
        *(float2*)(dst + j1)     = v2;
        *(float2*)(dst + j1 + 2) = v3;
    }
}

// ---------------- xproj layer 1: tiled GEMM, K=64 ----------------
__global__ void __launch_bounds__(256) xproj1_kernel(
    const float* __restrict__ wf, const float* __restrict__ bif, const float* __restrict__ bhf,
    const float* __restrict__ wr, const float* __restrict__ bir, const float* __restrict__ bhr)
{
    __shared__ float ws[32 * TW];
    __shared__ float fs[32 * TW];
    const int tid = threadIdx.x;
    const int s0 = blockIdx.x * 64;
    const int b  = blockIdx.y;
    const int d  = blockIdx.z;
    const float* w  = d ? wr : wf;
    const float* bi = d ? bir : bif;
    const float* bh = d ? bhr : bhf;

    const int sn  = tid & 127, skq = tid >> 7;
    const int xr  = tid & 63,  xkq = tid >> 6;
    int s = s0 + xr;
    int tsrc = d ? (1023 - s) : s;
    const float* wptr = w + sn * 64 + skq * 16;
    const float* hptr = g_h0 + ((size_t)b * 1024 + tsrc) * 64 + xkq * 8;

    const int nq = tid & 15;
    const int bq = tid >> 4;
    U64 acc[4][4];
    #pragma unroll
    for (int i = 0; i < 4; i++)
        #pragma unroll
        for (int j = 0; j < 4; j++) acc[i][j] = 0ull;

    #pragma unroll
    for (int ch = 0; ch < 2; ch++){
        if (ch){ __syncthreads(); }
        {
            const float4* src = (const float4*)(wptr + ch * 32);
            float4 v0 = src[0], v1 = src[1], v2 = src[2], v3 = src[3];
            int kb = skq * 16;
            ws[(kb+ 0)*TW + sn] = v0.x; ws[(kb+ 1)*TW + sn] = v0.y;
            ws[(kb+ 2)*TW + sn] = v0.z; ws[(kb+ 3)*TW + sn] = v0.w;
            ws[(kb+ 4)*TW + sn] = v1.x; ws[(kb+ 5)*TW + sn] = v1.y;
            ws[(kb+ 6)*TW + sn] = v1.z; ws[(kb+ 7)*TW + sn] = v1.w;
            ws[(kb+ 8)*TW + sn] = v2.x; ws[(kb+ 9)*TW + sn] = v2.y;
            ws[(kb+10)*TW + sn] = v2.z; ws[(kb+11)*TW + sn] = v2.w;
            ws[(kb+12)*TW + sn] = v3.x; ws[(kb+13)*TW + sn] = v3.y;
            ws[(kb+14)*TW + sn] = v3.z; ws[(kb+15)*TW + sn] = v3.w;
        }
        {
            const float4* src = (const float4*)(hptr + ch * 32);
            float4 u0 = src[0], u1 = src[1];
            int kb = xkq * 8;
            *(float2*)&fs[(kb+0)*TW + 2*xr] = make_float2(u0.x, u0.x);
            *(float2*)&fs[(kb+1)*TW + 2*xr] = make_float2(u0.y, u0.y);
            *(float2*)&fs[(kb+2)*TW + 2*xr] = make_float2(u0.z, u0.z);
            *(float2*)&fs[(kb+3)*TW + 2*xr] = make_float2(u0.w, u0.w);
            *(float2*)&fs[(kb+4)*TW + 2*xr] = make_float2(u1.x, u1.x);
            *(float2*)&fs[(kb+5)*TW + 2*xr] = make_float2(u1.y, u1.y);
            *(float2*)&fs[(kb+6)*TW + 2*xr] = make_float2(u1.z, u1.z);
            *(float2*)&fs[(kb+7)*TW + 2*xr] = make_float2(u1.w, u1.w);
        }
        __syncthreads();
        #pragma unroll
        for (int kk = 0; kk < 32; kk++){
            ulonglong2 wa = *(const ulonglong2*)&ws[kk*TW + nq*4];
            ulonglong2 wb = *(const ulonglong2*)&ws[kk*TW + 64 + nq*4];
            ulonglong2 xa = *(const ulonglong2*)&fs[kk*TW + bq*8];
            ulonglong2 xc = *(const ulonglong2*)&fs[kk*TW + bq*8 + 4];
            U64 xv0 = xa.x, xv1 = xa.y, xv2 = xc.x, xv3 = xc.y;
            ffma2(acc[0][0], xv0, wa.x); ffma2(acc[0][1], xv0, wa.y);
            ffma2(acc[0][2], xv0, wb.x); ffma2(acc[0][3], xv0, wb.y);
            ffma2(acc[1][0], xv1, wa.x); ffma2(acc[1][1], xv1, wa.y);
            ffma2(acc[1][2], xv1, wb.x); ffma2(acc[1][3], xv1, wb.y);
            ffma2(acc[2][0], xv2, wa.x); ffma2(acc[2][1], xv2, wa.y);
            ffma2(acc[2][2], xv2, wb.x); ffma2(acc[2][3], xv2, wb.y);
            ffma2(acc[3][0], xv3, wa.x); ffma2(acc[3][1], xv3, wa.y);
            ffma2(acc[3][2], xv3, wb.x); ffma2(acc[3][3], xv3, wb.y);
        }
    }

    int j0 = nq * 4, j1 = 64 + nq * 4;
    float bv[8];
    #pragma unroll
    for (int q = 0; q < 4; q++){ bv[q] = bi[j0+q] + bh[j0+q]; bv[4+q] = bi[j1+q] + bh[j1+q]; }

    float* base = g_xp + ((size_t)(d * 64 + b) * 1024 + s0) * 128;
    #pragma unroll
    for (int b4 = 0; b4 < 4; b4++){
        float* dst = base + (size_t)(bq * 4 + b4) * 128;
        float2 v0 = unpk(acc[b4][0]); v0.x += bv[0]; v0.y += bv[1];
        float2 v1 = unpk(acc[b4][1]); v1.x += bv[2]; v1.y += bv[3];
        float2 v2 = unpk(acc[b4][2]); v2.x += bv[4]; v2.y += bv[5];
        float2 v3 = unpk(acc[b4][3]); v3.x += bv[6]; v3.y += bv[7];
        *(float2*)(dst + j0)     = v0;
        *(float2*)(dst + j0 + 2) = v1;
        *(float2*)(dst + j1)     = v2;
        *(float2*)(dst + j1 + 2) = v3;
    }
}

// ---------------- LSTM: 4 warps, k-partitioned units, gates in-warp via shfl ----------------
// warp w owns units [8w,8w+8); lane = 4*ulocal + gsel; gate order gsel {0,1,2,3} -> pytorch {i,g,f,o}
__global__ void __launch_bounds__(128, 1) lstm_kernel(
    const float* __restrict__ whh_f, const float* __restrict__ whh_r, int outsel)
{
    const int blk = blockIdx.x;
    const int d = blk >> 6, b = blk & 63;
    const int tid = threadIdx.x;
    const int wid = tid >> 5;
    const int l   = tid & 31;
    const int gsel   = l & 3;
    const int ulocal = l >> 2;
    const int unit   = wid * 8 + ulocal;
    const int gate   = (gsel == 1) ? 2 : ((gsel == 2) ? 1 : gsel);  // {i,g,f,o} -> rows {0,2,1,3}
    float* hout = outsel ? g_h1 : g_h0;
    const float* whh = d ? whh_r : whh_f;

    U64 wp[16];   // Whh row (gate, unit): 32 floats
    {
        const ulonglong2* wr2 = (const ulonglong2*)(whh + (gate * 32 + unit) * 32);
        #pragma unroll
        for (int r = 0; r < 8; r++){ ulonglong2 v = wr2[r]; wp[2*r] = v.x; wp[2*r+1] = v.y; }
    }

    __shared__ __align__(16) float hs[2][32];
    if (tid < 32){ hs[0][tid] = 0.0f; hs[1][tid] = 0.0f; }
    float c = 0.0f;
    __syncthreads();

    const float* xq = g_xp + (size_t)(d * 64 + b) * 1024 * 128 + gate * 32 + unit;
    float* outp = hout + (size_t)b * 1024 * 64 + d * 32 + unit;
    const int lbase = l & ~3;

    // 4-deep prefetch: one xp value per lane per step
    float cur0 = xq[0], cur1 = xq[128], cur2 = xq[256], cur3 = xq[384];

    #define LSTM_STEP(SS, XV)                                                 \
    {                                                                         \
        U64 a0 = 0ull, a1 = 0ull;                                             \
        const ulonglong2* h2 = (const ulonglong2*)hs[(SS) & 1];               \
        _Pragma("unroll")                                                     \
        for (int r = 0; r < 8; r++){                                          \
            ulonglong2 hv = h2[r];                                            \
            ffma2(a0, hv.x, wp[2*r]);                                         \
            ffma2(a1, hv.y, wp[2*r+1]);                                       \
        }                                                                     \
        float pre = (XV) + sum2(add2(a0, a1));                                \
        float act = (gsel == 1) ? tanha(pre) : siga(pre);                     \
        float iv = __shfl_sync(0xffffffffu, act, lbase);                      \
        float gv = __shfl_sync(0xffffffffu, act, lbase + 1);                  \
        float fv = __shfl_sync(0xffffffffu, act, lbase + 2);                  \
        float ov = __shfl_sync(0xffffffffu, act, lbase + 3);                  \
        c = fmaf(fv, c, iv * gv);                                             \
        float hval = ov * tanha(c);                                           \
        if (gsel == 0){                                                       \
            hs[((SS) + 1) & 1][unit] = hval;                                  \
            int tout = d ? (1023 - (SS)) : (SS);                              \
            outp[(size_t)tout * 64] = hval;                                   \
        }                                                                     \
        __syncthreads();                                                      \
    }

    for (int s = 0; s < 1024; s += 4){
        const float* q = xq + (size_t)(s + 4) * 128;
        float n0 = q[0], n1 = q[128], n2 = q[256], n3 = q[384];

        LSTM_STEP(s + 0, cur0)
        LSTM_STEP(s + 1, cur1)
        LSTM_STEP(s + 2, cur2)
        LSTM_STEP(s + 3, cur3)

        cur0 = n0; cur1 = n1; cur2 = n2; cur3 = n3;
    }
    #undef LSTM_STEP
}

// ---------------- fc via mma.sync bf16 3-term split (fc1 & fc2) ----------------
#define MB_WH 0
#define MB_WL 8192
#define MB_XH 16384
#define MB_XL 20480
#define MB_BUF 24576

__global__ void __launch_bounds__(128) fc_mma_kernel(
    const float* __restrict__ W, const float* __restrict__ Xg,
    float* __restrict__ part, int K, int N, int nchunks)
{
    __shared__ __align__(128) char smb[2 * MB_BUF];  // 48KB
    const int tid  = threadIdx.x;
    const int lane = tid & 31;
    const int wid  = tid >> 5;
    const int m0out  = blockIdx.x * 128;
    const int kstart = blockIdx.y * (nchunks * 32);

    const int kq    = tid & 7;
    const int rbase = tid >> 3;

    const float* wg = W  + (size_t)(m0out + rbase) * K + kstart + kq * 4;
    const float* xg = Xg + (size_t)rbase * K + kstart + kq * 4;

    const uint32_t sb = smem_u32(smb);

    const int arow = wid * 16 + ((lane >> 3) & 1) * 8 + (lane & 7);
    const int asw  = (arow >> 1) & 3;
    const int akb  = lane >> 4;
    const uint32_t aoff = (uint32_t)(arow * 64);
    const int brow = ((lane >> 4) & 1) * 8 + (lane & 7);
    const int bsw  = (brow >> 1) & 3;
    const int bkb  = (lane >> 3) & 1;
    const uint32_t boff = (uint32_t)(brow * 64);

    float acc[16][4];
    #pragma unroll
    for (int i = 0; i < 16; i++)
        #pragma unroll
        for (int j = 0; j < 4; j++) acc[i][j] = 0.0f;

    float4 wv[8], xv[4];
    #pragma unroll
    for (int i = 0; i < 8; i++) wv[i] = *(const float4*)(wg + (size_t)i * 16 * K);
    #pragma unroll
    for (int i = 0; i < 4; i++) xv[i] = *(const float4*)(xg + (size_t)i * 16 * K);

    const int so_base = (kq & 1) * 8;
    for (int ch = 0; ch < nchunks; ch++){
        char* bufc = smb + (ch & 1) * MB_BUF;
        #pragma unroll
        for (int i = 0; i < 8; i++){
            float4 v = wv[i];
            int row = rbase + i * 16;
            uint32_t h0 = cvt_bf2(v.x, v.y);
            uint32_t l0 = cvt_bf2(v.x - __uint_as_float(h0 << 16),
                                  v.y - __uint_as_float(h0 & 0xFFFF0000u));
            uint32_t h1 = cvt_bf2(v.z, v.w);
            uint32_t l1 = cvt_bf2(v.z - __uint_as_float(h1 << 16),
                                  v.w - __uint_as_float(h1 & 0xFFFF0000u));
            int so = row * 64 + ((((kq >> 1) ^ ((row >> 1) & 3)) << 4) | so_base);
            *(uint2*)(bufc + MB_WH + so) = make_uint2(h0, h1);
            *(uint2*)(bufc + MB_WL + so) = make_uint2(l0, l1);
        }
        #pragma unroll
        for (int i = 0; i < 4; i++){
            float4 v = xv[i];
            int row = rbase + i * 16;
            uint32_t h0 = cvt_bf2(v.x, v.y);
            uint32_t l0 = cvt_bf2(v.x - __uint_as_float(h0 << 16),
                                  v.y - __uint_as_float(h0 & 0xFFFF0000u));
            uint32_t h1 = cvt_bf2(v.z, v.w);
            uint32_t l1 = cvt_bf2(v.z - __uint_as_float(h1 << 16),
                                  v.w - __uint_as_float(h1 & 0xFFFF0000u));
            int so = row * 64 + ((((kq >> 1) ^ ((row >> 1) & 3)) << 4) | so_base);
            *(uint2*)(bufc + MB_XH + so) = make_uint2(h0, h1);
            *(uint2*)(bufc + MB_XL + so) = make_uint2(l0, l1);
        }
        __syncthreads();

        if (ch + 1 < nchunks){
            #pragma unroll
            for (int i = 0; i < 8; i++) wv[i] = *(const float4*)(wg + (size_t)i * 16 * K + (ch + 1) * 32);
            #pragma unroll
            for (int i = 0; i < 4; i++) xv[i] = *(const float4*)(xg + (size_t)i * 16 * K + (ch + 1) * 32);
        }

        const uint32_t sbuf = sb + (ch & 1) * MB_BUF;
        #pragma unroll
        for (int kt = 0; kt < 2; kt++){
            uint32_t ahi[4], alo[4];
            uint32_t aaddr = sbuf + MB_XH + aoff + (uint32_t)((((kt << 1) | akb) ^ asw) << 4);
            ldm4(ahi, aaddr);
            ldm4(alo, aaddr + (MB_XL - MB_XH));
            #pragma unroll
            for (int ntp = 0; ntp < 8; ntp++){
                uint32_t bhi[4], blo[4];
                uint32_t baddr = sbuf + MB_WH + (uint32_t)(ntp * 1024) + boff
                               + (uint32_t)((((kt << 1) | bkb) ^ bsw) << 4);
                ldm4(bhi, baddr);
                ldm4(blo, baddr + (MB_WL - MB_WH));
                mma_bf(acc[2*ntp],   ahi, bhi[0], bhi[1]);
                mma_bf(acc[2*ntp],   alo, bhi[0], bhi[1]);
                mma_bf(acc[2*ntp],   ahi, blo[0], blo[1]);
                mma_bf(acc[2*ntp+1], ahi, bhi[2], bhi[3]);
                mma_bf(acc[2*ntp+1], alo, bhi[2], bhi[3]);
                mma_bf(acc[2*ntp+1], ahi, blo[2], blo[3]);
            }
        }
        __syncthreads();
    }

    {
        int bat  = wid * 16 + (lane >> 2);
        int colb = m0out + (lane & 3) * 2;
        float* d0 = part + ((size_t)blockIdx.y * 64 + bat) * N + colb;
        float* d1 = d0 + (size_t)8 * N;
        #pragma unroll
        for (int nt = 0; nt < 16; nt++){
            *(float2*)(d0 + nt * 8) = make_float2(acc[nt][0], acc[nt][1]);
            *(float2*)(d1 + nt * 8) = make_float2(acc[nt][2], acc[nt][3]);
        }
    }
}

// ---------------- split-K reductions ----------------
__global__ void reduce1_kernel(const float* __restrict__ bias){
    int i = blockIdx.x * 256 + threadIdx.x;   // 131072
    int m = i & 2047, b = i >> 11;
    float acc = bias[m];
    #pragma unroll
    for (int s = 0; s < 64; s++) acc += g_part1[((size_t)s * 64 + b) * 2048 + m];
    g_hidden[i] = fmaxf(acc, 0.0f);
}

__global__ void reduce2_kernel(const float* __restrict__ bias, float* __restrict__ out){
    int i = blockIdx.x * 256 + threadIdx.x;   // 589824
    int n = i % 9216, b = i / 9216;
    float acc = bias[n];
    #pragma unroll
    for (int s = 0; s < 8; s++) acc += g_part2[((size_t)s * 64 + b) * 9216 + n];
    out[i] = acc;
}

// ---------------- launcher ----------------
extern "C" void kernel_launch(void* const* d_in, const int* in_sizes, int n_in,
                              void* d_out, int out_size)
{
    const float* x     = (const float*)d_in[0];
    const float* wih0  = (const float*)d_in[1];
    const float* whh0  = (const float*)d_in[2];
    const float* bih0  = (const float*)d_in[3];
    const float* bhh0  = (const float*)d_in[4];
    const float* wih0r = (const float*)d_in[5];
    const float* whh0r = (const float*)d_in[6];
    const float* bih0r = (const float*)d_in[7];
    const float* bhh0r = (const float*)d_in[8];
    const float* wih1  = (const float*)d_in[9];
    const float* whh1  = (const float*)d_in[10];
    const float* bih1  = (const float*)d_in[11];
    const float* bhh1  = (const float*)d_in[12];
    const float* wih1r = (const float*)d_in[13];
    const float* whh1r = (const float*)d_in[14];
    const float* bih1r = (const float*)d_in[15];
    const float* bhh1r = (const float*)d_in[16];
    const float* fc1w  = (const float*)d_in[17];
    const float* fc1b  = (const float*)d_in[18];
    const float* fc2w  = (const float*)d_in[19];
    const float* fc2b  = (const float*)d_in[20];
    float* out = (float*)d_out;

    float* d_h1;     cudaGetSymbolAddress((void**)&d_h1,     g_h1);
    float* d_hidden; cudaGetSymbolAddress((void**)&d_hidden, g_hidden);
    float* d_part1;  cudaGetSymbolAddress((void**)&d_part1,  g_part1);
    float* d_part2;  cudaGetSymbolAddress((void**)&d_part2,  g_part2);

    xproj0_kernel<<<dim3(16, 64, 2), 256>>>(x, wih0, bih0, bhh0, wih0r, bih0r, bhh0r);
    lstm_kernel<<<128, 128>>>(whh0, whh0r, 0);
    xproj1_kernel<<<dim3(16, 64, 2), 256>>>(wih1, bih1, bhh1, wih1r, bih1r, bhh1r);
    lstm_kernel<<<128, 128>>>(whh1, whh1r, 1);

    // fc1: grid (16 wrow-tiles of 128, 64 k-splits of 1024 => 32 chunks)
    fc_mma_kernel<<<dim3(16, 64), 128>>>(fc1w, d_h1, d_part1, 65536, 2048, 32);
    reduce1_kernel<<<512, 256>>>(fc1b);

    // fc2: grid (72 wrow-tiles of 128, 8 k-splits of 256 => 8 chunks)
    fc_mma_kernel<<<dim3(72, 8), 128>>>(fc2w, d_hidden, d_part2, 2048, 9216, 8);
    reduce2_kernel<<<2304, 256>>>(fc2b, out);
}